// round 13
// baseline (speedup 1.0000x reference)
#include <cuda_runtime.h>
#include <cuda_bf16.h>
#include <cstdint>

// Problem constants
#define NUM_CHIPS 4
#define SEQ 1024
#define HIDDEN 2048
#define TOP_K 4
#define N_EXPERTS 32
#define MAX_TOK 1024
#define META_LEN 8
#define N_PER_CHIP (SEQ * TOP_K)           // 4096
#define N_TOTAL (NUM_CHIPS * N_PER_CHIP)   // 16384 assignments
#define N_CHUNKS (N_TOTAL / 32)            // 512 warp-chunks, chip-major
#define TOTAL_SLOTS (N_EXPERTS * MAX_TOK)  // 32768
#define BUF_ELEMS ((size_t)TOTAL_SLOTS * HIDDEN)
#define META_OFF  BUF_ELEMS
#define CNT_OFF   (BUF_ELEMS + (size_t)TOTAL_SLOTS * META_LEN)

#define NB 444                  // persistent blocks: 3/SM @ 512 thr -> fully co-resident
#define THREADS 512
#define PLAN_BLOCKS 32          // blocks 0..31 plan 16 chunks each; block 32 emits totals

// Scratch (no allocations allowed). g_bar is MONOTONE across graph replays:
// exactly NB tickets per replay -> window math exact, no reset kernel.
__device__ int g_src[TOTAL_SLOTS];   // slot -> assignment id (first cnt_e per expert valid)
__device__ int g_cnt[N_EXPERTS];     // per-expert totals
__device__ unsigned g_bar;           // monotone barrier tickets

__global__ void __launch_bounds__(THREADS, 3) dispatch_kernel(
    const float* __restrict__ x, const float* __restrict__ w,
    const int* __restrict__ idx, float* __restrict__ out)
{
    __shared__ int s_hist[N_EXPERTS];        // histogram of preceding region
    __shared__ int s_cnt[16][N_EXPERTS];     // per-warp per-expert counts (this block)
    __shared__ int s_pref[N_EXPERTS][16];    // exclusive warp prefix per expert

    const int warp = threadIdx.x >> 5;       // 0..15
    const int lane = threadIdx.x & 31;
    const unsigned lt = (1u << lane) - 1u;
    const int b = blockIdx.x;

    // ---------------- Phase 1: planning (blocks 0..32), barrier-free -------
    if (b <= PLAN_BLOCKS) {
        if (threadIdx.x < N_EXPERTS) s_hist[threadIdx.x] = 0;
        s_cnt[warp][lane] = 0;
        __syncthreads();

        if (b == PLAN_BLOCKS) {
            // Totals block: histogram ALL 512 chunks.
#pragma unroll 4
            for (int ch = warp; ch < N_CHUNKS; ch += 16) {
                const int e = __ldg(&idx[ch * 32 + lane]);
                const unsigned m = __match_any_sync(0xFFFFFFFFu, e);
                if ((m & lt) == 0) atomicAdd(&s_hist[e], __popc(m));
            }
            __syncthreads();
            if (threadIdx.x < N_EXPERTS) {
                g_cnt[threadIdx.x] = s_hist[threadIdx.x];
                out[CNT_OFF + threadIdx.x] = (float)s_hist[threadIdx.x];
            }
        } else {
            // Own chunk (warp w owns chunk b*16+w): rank + per-warp counts.
            const int a = (b * 16 + warp) * 32 + lane;
            const int e = __ldg(&idx[a]);
            const unsigned m = __match_any_sync(0xFFFFFFFFu, e);
            const int rk = __popc(m & lt);
            if (rk == 0) s_cnt[warp][e] = __popc(m);  // leaders: distinct e, no conflict

            // Redundant histogram of preceding chunks [0, b*16); unrolled for MLP.
#pragma unroll 4
            for (int ch = warp; ch < b * 16; ch += 16) {
                const int pe = __ldg(&idx[ch * 32 + lane]);
                const unsigned pm = __match_any_sync(0xFFFFFFFFu, pe);
                if ((pm & lt) == 0) atomicAdd(&s_hist[pe], __popc(pm));
            }
            __syncthreads();

            // Exclusive prefix over the 16 warps, per expert (width-16 scans).
            {
                const int e2 = threadIdx.x >> 4;
                const int wi = threadIdx.x & 15;
                const int c  = s_cnt[wi][e2];
                int s = c;
#pragma unroll
                for (int d = 1; d < 16; d <<= 1) {
                    int t = __shfl_up_sync(0xFFFFFFFFu, s, d, 16);
                    if (wi >= d) s += t;
                }
                s_pref[e2][wi] = s - c;
            }
            __syncthreads();

            // Emit inverse map.
            const int slot = e * MAX_TOK + s_hist[e] + s_pref[e][warp] + rk;
            g_src[slot] = a;
        }
    }

    // ---------------- One monotone-window grid barrier ---------------------
    __syncthreads();
    __threadfence();
    if (threadIdx.x == 0) {
        const unsigned t = atomicAdd(&g_bar, 1u);
        const unsigned target = (t / NB + 1u) * NB;   // exactly NB tickets per replay
        while (atomicAdd(&g_bar, 0u) < target) { }
    }
    __syncthreads();
    __threadfence();

    // ---------------- Phase 2: gather, software-pipelined 2 slots/trip -----
    const int t = threadIdx.x;
    const float4 z = make_float4(0.f, 0.f, 0.f, 0.f);

    for (int s0 = b; s0 < TOTAL_SLOTS; s0 += 2 * NB) {
        const int s1 = s0 + NB;
        const bool hasB = (s1 < TOTAL_SLOTS);

        // Resolve both slots, issue both loads before any store.
        const int eA  = s0 >> 10;
        const bool fA = (s0 & (MAX_TOK - 1)) < g_cnt[eA];
        int aA = 0;
        float4 vA = z;
        if (fA) {
            aA = g_src[s0];
            const int cA = aA >> 12, tokA = (aA & (N_PER_CHIP - 1)) >> 2;
            vA = reinterpret_cast<const float4*>(x + ((size_t)cA * SEQ + tokA) * HIDDEN)[t];
        }

        int eB = 0; bool fB = false; int aB = 0;
        float4 vB = z;
        if (hasB) {
            eB = s1 >> 10;
            fB = (s1 & (MAX_TOK - 1)) < g_cnt[eB];
            if (fB) {
                aB = g_src[s1];
                const int cB = aB >> 12, tokB = (aB & (N_PER_CHIP - 1)) >> 2;
                vB = reinterpret_cast<const float4*>(x + ((size_t)cB * SEQ + tokB) * HIDDEN)[t];
            }
        }

        // Stores (row A, row B, then both meta).
        reinterpret_cast<float4*>(out + (size_t)s0 * HIDDEN)[t] = vA;
        if (hasB)
            reinterpret_cast<float4*>(out + (size_t)s1 * HIDDEN)[t] = vB;

        if (t == 0) {
            float4* mdA = reinterpret_cast<float4*>(out + META_OFF + (size_t)s0 * META_LEN);
            if (fA) {
                const int cA = aA >> 12, nA = aA & (N_PER_CHIP - 1);
                unsigned short bits = __bfloat16_as_ushort(__float2bfloat16(w[aA]));
                mdA[0] = make_float4((float)cA, (float)(nA >> 2), (float)(nA & 3), (float)eA);
                mdA[1] = make_float4((float)bits, 0.f, 0.f, 0.f);
            } else {
                const float4 neg = make_float4(-1.f, -1.f, -1.f, -1.f);
                mdA[0] = neg; mdA[1] = neg;
            }
            if (hasB) {
                float4* mdB = reinterpret_cast<float4*>(out + META_OFF + (size_t)s1 * META_LEN);
                if (fB) {
                    const int cB = aB >> 12, nB = aB & (N_PER_CHIP - 1);
                    unsigned short bits = __bfloat16_as_ushort(__float2bfloat16(w[aB]));
                    mdB[0] = make_float4((float)cB, (float)(nB >> 2), (float)(nB & 3), (float)eB);
                    mdB[1] = make_float4((float)bits, 0.f, 0.f, 0.f);
                } else {
                    const float4 neg = make_float4(-1.f, -1.f, -1.f, -1.f);
                    mdB[0] = neg; mdB[1] = neg;
                }
            }
        }
    }
}

// ---------------------------------------------------------------------------
extern "C" void kernel_launch(void* const* d_in, const int* in_sizes, int n_in,
                              void* d_out, int out_size) {
    const float* x   = (const float*)d_in[0];   // [4,1024,2048] f32
    const float* wts = (const float*)d_in[1];   // [4,1024,4]    f32
    const int*   ind = (const int*)  d_in[2];   // [4,1024,4]    i32
    float* out = (float*)d_out;

    dispatch_kernel<<<NB, THREADS>>>(x, wts, ind, out);
}

// round 14
// speedup vs baseline: 1.1263x; 1.1263x over previous
#include <cuda_runtime.h>
#include <cuda_bf16.h>
#include <cstdint>

// Problem constants
#define NUM_CHIPS 4
#define SEQ 1024
#define HIDDEN 2048
#define TOP_K 4
#define N_EXPERTS 32
#define MAX_TOK 1024
#define META_LEN 8
#define N_PER_CHIP (SEQ * TOP_K)           // 4096
#define N_TOTAL (NUM_CHIPS * N_PER_CHIP)   // 16384 assignments
#define N_CHUNKS (N_TOTAL / 32)            // 512 warp-chunks, chip-major
#define TOTAL_SLOTS (N_EXPERTS * MAX_TOK)  // 32768
#define BUF_ELEMS ((size_t)TOTAL_SLOTS * HIDDEN)
#define META_OFF  BUF_ELEMS
#define CNT_OFF   (BUF_ELEMS + (size_t)TOTAL_SLOTS * META_LEN)

#define PLAN_BLOCKS 16          // blocks 0..15 plan 32 chunks each; block 16 emits totals

// Scratch (no allocations allowed)
__device__ int g_src[TOTAL_SLOTS];   // slot -> assignment id (first cnt_e per expert valid)
__device__ int g_cnt[N_EXPERTS];     // per-expert totals

// ---------------------------------------------------------------------------
// Planning: 17 blocks x 1024 threads, NO cross-block sync. Each block
// redundantly histograms the assignments preceding its region:
//   slot(a) = e*1024 + hist_before_block[e] + within_block_prefix[e] + rank
// Block 16 computes the full histogram -> g_cnt + output counters.
// Ends with a PDL trigger so the gather grid pre-launches.
// ---------------------------------------------------------------------------
__global__ void __launch_bounds__(1024) plan_kernel(const int* __restrict__ idx,
                                                    float* __restrict__ out) {
    __shared__ int s_hist[N_EXPERTS];          // histogram of preceding region
    __shared__ int s_cnt[32][N_EXPERTS];       // per-warp per-expert counts (this block)
    __shared__ int s_pref[N_EXPERTS][32];      // exclusive warp prefix per expert

    const int warp = threadIdx.x >> 5;
    const int lane = threadIdx.x & 31;
    const unsigned lt = (1u << lane) - 1u;
    const int b = blockIdx.x;

    if (threadIdx.x < N_EXPERTS) s_hist[threadIdx.x] = 0;
    s_cnt[warp][lane] = 0;

    if (b == PLAN_BLOCKS) {
        // Totals block: histogram ALL 512 chunks.
        __syncthreads();
#pragma unroll 4
        for (int ch = warp; ch < N_CHUNKS; ch += 32) {
            const int e = __ldg(&idx[ch * 32 + lane]);
            const unsigned m = __match_any_sync(0xFFFFFFFFu, e);
            if ((m & lt) == 0) atomicAdd(&s_hist[e], __popc(m));
        }
        __syncthreads();
        if (threadIdx.x < N_EXPERTS) {
            g_cnt[threadIdx.x] = s_hist[threadIdx.x];
            out[CNT_OFF + threadIdx.x] = (float)s_hist[threadIdx.x];
        }
        __threadfence();
        cudaTriggerProgrammaticLaunchCompletion();
        return;
    }

    // Own chunk: rank + count (warp w owns chunk b*32+w).
    const int a = (b * 32 + warp) * 32 + lane;
    const int e = __ldg(&idx[a]);
    const unsigned m = __match_any_sync(0xFFFFFFFFu, e);
    const int rk = __popc(m & lt);
    __syncwarp();
    if (rk == 0) s_cnt[warp][e] = __popc(m);   // leaders hold distinct e: no conflict

    // Redundant histogram of preceding region [0, b*32) chunks (MLP via unroll).
#pragma unroll 4
    for (int ch = warp; ch < b * 32; ch += 32) {
        const int pe = __ldg(&idx[ch * 32 + lane]);
        const unsigned pm = __match_any_sync(0xFFFFFFFFu, pe);
        if ((pm & lt) == 0) atomicAdd(&s_hist[pe], __popc(pm));
    }
    __syncthreads();

    // Warp ex scans expert ex's 32 per-warp counts (exclusive).
    {
        const int ex = warp;
        const int c = s_cnt[lane][ex];
        int s = c;
#pragma unroll
        for (int d = 1; d < 32; d <<= 1) {
            int t = __shfl_up_sync(0xFFFFFFFFu, s, d);
            if (lane >= d) s += t;
        }
        s_pref[ex][lane] = s - c;
    }
    __syncthreads();

    // Emit inverse map, then PDL trigger.
    const int slot = e * MAX_TOK + s_hist[e] + s_pref[e][warp] + rk;
    g_src[slot] = a;
    __threadfence();
    cudaTriggerProgrammaticLaunchCompletion();
}

// ---------------------------------------------------------------------------
// Gather: the proven fastest shape — one block per slot, 256 threads, plain
// float4 loads/stores (measured 52.5us @ 68% DRAM). PDL-gated at entry.
// ---------------------------------------------------------------------------
__global__ void __launch_bounds__(256) gather_kernel(const float* __restrict__ x,
                                                     const float* __restrict__ w,
                                                     float* __restrict__ out) {
    cudaGridDependencySynchronize();

    const int slot = blockIdx.x;
    const int e    = slot >> 10;
    const int si   = slot & (MAX_TOK - 1);
    const int t    = threadIdx.x;
    float4* dst = reinterpret_cast<float4*>(out + (size_t)slot * HIDDEN);
    float4* md  = reinterpret_cast<float4*>(out + META_OFF + (size_t)slot * META_LEN);

    if (si < g_cnt[e]) {
        const int a   = g_src[slot];
        const int c   = a >> 12;
        const int n   = a & (N_PER_CHIP - 1);
        const int tok = n >> 2;
        const float4* src =
            reinterpret_cast<const float4*>(x + ((size_t)c * SEQ + tok) * HIDDEN);
        float4 v0 = src[t];
        float4 v1 = src[t + 256];
        dst[t]       = v0;
        dst[t + 256] = v1;
        if (t == 0) {
            __nv_bfloat16 hb = __float2bfloat16(w[a]);
            unsigned short bits = __bfloat16_as_ushort(hb);
            md[0] = make_float4((float)c, (float)tok, (float)(n & 3), (float)e);
            md[1] = make_float4((float)bits, 0.f, 0.f, 0.f);
        }
    } else {
        const float4 z = make_float4(0.f, 0.f, 0.f, 0.f);
        dst[t]       = z;
        dst[t + 256] = z;
        if (t == 0) {
            const float4 neg = make_float4(-1.f, -1.f, -1.f, -1.f);
            md[0] = neg;
            md[1] = neg;
        }
    }
}

// ---------------------------------------------------------------------------
extern "C" void kernel_launch(void* const* d_in, const int* in_sizes, int n_in,
                              void* d_out, int out_size) {
    const float* x   = (const float*)d_in[0];   // [4,1024,2048] f32
    const float* wts = (const float*)d_in[1];   // [4,1024,4]    f32
    const int*   ind = (const int*)  d_in[2];   // [4,1024,4]    i32
    float* out = (float*)d_out;

    plan_kernel<<<PLAN_BLOCKS + 1, 1024>>>(ind, out);

    // Gather with programmatic dependent launch: pre-spawn while plan drains.
    cudaLaunchAttribute attrs[1];
    attrs[0].id = cudaLaunchAttributeProgrammaticStreamSerialization;
    attrs[0].val.programmaticStreamSerializationAllowed = 1;

    cudaLaunchConfig_t cfg = {};
    cfg.gridDim  = dim3(TOTAL_SLOTS, 1, 1);
    cfg.blockDim = dim3(256, 1, 1);
    cfg.dynamicSmemBytes = 0;
    cfg.stream = 0;
    cfg.attrs = attrs;
    cfg.numAttrs = 1;

    cudaLaunchKernelEx(&cfg, gather_kernel, x, wts, out);
}